// round 16
// baseline (speedup 1.0000x reference)
#include <cuda_runtime.h>
#include <cuda_bf16.h>
#include <cstdint>

#define PVOL   29791
#define MROWS  119164
#define D1     512
#define KK     128
#define BM     64
#define BN     128
#define NCOL   4
#define NT     128

// smem byte offsets
#define O_A0    0          // 64x128 bf16 = 16384
#define O_A1    16384
#define O_B0    32768      // 128x128 bf16 = 32768
#define O_B1    65536
#define O_YSQP  98304      // 2*64 f32
#define O_YSQ   98816      // 64 f32
#define O_WSQ   99072      // 128 f32
#define SMEM_BYTES 99584

// bf16 element index with 16B-chunk XOR swizzle (row&7)
__device__ __forceinline__ int idx16(int row, int k) {
    return row * 128 + ((((k >> 3) ^ (row & 7))) << 3) + (k & 7);
}

__device__ __forceinline__ uint32_t s2u(const void* p) {
    uint32_t a;
    asm("{ .reg .u64 t; cvta.to.shared.u64 t, %1; cvt.u32.u64 %0, t; }" : "=r"(a) : "l"(p));
    return a;
}
__device__ __forceinline__ void ldsm4(uint32_t& r0, uint32_t& r1, uint32_t& r2, uint32_t& r3,
                                      uint32_t addr) {
    asm volatile("ldmatrix.sync.aligned.m8n8.x4.shared.b16 {%0,%1,%2,%3}, [%4];"
                 : "=r"(r0), "=r"(r1), "=r"(r2), "=r"(r3) : "r"(addr));
}
__device__ __forceinline__ void mma_bf16(float* d, const uint32_t* a, uint32_t b0, uint32_t b1) {
    asm volatile(
        "mma.sync.aligned.m16n8k16.row.col.f32.bf16.bf16.f32 "
        "{%0,%1,%2,%3}, {%4,%5,%6,%7}, {%8,%9}, {%0,%1,%2,%3};"
        : "+f"(d[0]), "+f"(d[1]), "+f"(d[2]), "+f"(d[3])
        : "r"(a[0]), "r"(a[1]), "r"(a[2]), "r"(a[3]), "r"(b0), "r"(b1));
}
__device__ __forceinline__ unsigned short bfbits(float v) {
    return __bfloat16_as_ushort(__float2bfloat16(v));
}
__device__ __forceinline__ float bf2f(unsigned short u) {
    __nv_bfloat16_raw raw; raw.x = u;
    return __bfloat162float(*(__nv_bfloat16*)&raw);
}

__global__ __launch_bounds__(NT, 2)
void gk_kernel(const float* __restrict__ x, const float* __restrict__ w,
               float* __restrict__ out) {
    extern __shared__ __align__(16) char smem[];
    uint16_t* sA0 = (uint16_t*)(smem + O_A0);
    uint16_t* sA1 = (uint16_t*)(smem + O_A1);
    float*    ysqp = (float*)(smem + O_YSQP);
    float*    ysq  = (float*)(smem + O_YSQ);
    float*    wsq  = (float*)(smem + O_WSQ);

    const uint32_t aA0 = s2u(smem + O_A0);
    const uint32_t aA1 = s2u(smem + O_A1);
    const uint32_t aB0 = s2u(smem + O_B0);
    const uint32_t aB1 = s2u(smem + O_B1);

    const int tid  = threadIdx.x;
    const int wid  = tid >> 5;
    const int lane = tid & 31;
    const int row0 = blockIdx.x * BM;

    // ---------------- gather A -> 2-term bf16 tiles + ||y||^2 ----------------
    {
        const int m    = tid & 63;
        const int half = tid >> 6;           // kw bit
        const int row  = row0 + m;
        float s = 0.0f;
        if (row < MROWS) {
            const int n   = row / PVOL;
            const int p   = row - n * PVOL;
            const int d   = p / 961;
            const int rem = p - d * 961;
            const int h   = rem / 31;
            const int wx  = rem - h * 31;
            const long base = (long)n * 524288 + d * 1024 + h * 32 + wx + half;
            #pragma unroll 4
            for (int it = 0; it < 64; ++it) {
                const int c  = it >> 2;
                const int kd = (it >> 1) & 1;
                const int kh = it & 1;
                const int k  = c * 8 + kd * 4 + kh * 2 + half;
                const float v = x[base + (long)c * 32768 + kd * 1024 + kh * 32];
                const unsigned short u0 = bfbits(v);
                const unsigned short u1 = bfbits(v - bf2f(u0));
                const int o = idx16(m, k);
                sA0[o] = u0;
                sA1[o] = u1;
                s = fmaf(v, v, s);
            }
        } else {
            #pragma unroll 4
            for (int it = 0; it < 64; ++it) {
                const int k = (it >> 2) * 8 + (((it >> 1) & 1) << 2) + ((it & 1) << 1) + half;
                const int o = idx16(m, k);
                sA0[o] = 0;
                sA1[o] = 0;
            }
        }
        ysqp[half * 64 + m] = s;
    }
    __syncthreads();
    if (tid < 64) ysq[tid] = ysqp[tid] + ysqp[64 + tid];

    // ---- per-warp fragment geometry: warp tile 32(m) x 64(n), grid 2x2 ----
    const int m0 = (wid >> 1) * 32;
    const int n0 = (wid & 1) * 64;
    const int r    = lane & 7;
    const int midx = lane >> 3;
    const int mi1  = (midx & 1) * 8;
    const int kmi  = midx >> 1;
    const uint32_t rowA0 = (uint32_t)(m0 + mi1 + r) * 256u;
    const uint32_t rowA1 = rowA0 + 16u * 256u;
    uint32_t rowB[4];
    #pragma unroll
    for (int u = 0; u < 4; ++u)
        rowB[u] = (uint32_t)(n0 + u * 16 + mi1 + r) * 256u;

    const int c  = lane & 3;
    const int rg = lane >> 2;

    __syncthreads();   // ysq visible

    // ---- hoisted per-thread output rows + ||y||^2 ----
    long obase[4];
    bool ovalid[4];
    float ysf[4];
    #pragma unroll
    for (int q = 0; q < 4; ++q) {
        const int mloc = m0 + q * 8 + rg;
        const int row  = row0 + mloc;
        ysf[q] = ysq[mloc];
        ovalid[q] = row < MROWS;
        if (ovalid[q]) {
            const int n = row / PVOL;
            const int p = row - n * PVOL;
            obase[q] = (long)n * D1 * PVOL + p;
        } else obase[q] = 0;
    }

    for (int iter = 0; iter < NCOL; ++iter) {
        const int col0 = iter * BN;

        // ------------- fill B (2-term bf16, STS.128) + ||w||^2 --------------
        {
            const int nn = tid;                  // one column per thread
            const float* wr = w + (long)(col0 + nn) * KK;
            float s = 0.0f;
            #pragma unroll 4
            for (int j = 0; j < 16; ++j) {       // 8 k per chunk
                const float4 va = *(const float4*)(wr + j * 8);
                const float4 vb = *(const float4*)(wr + j * 8 + 4);
                const float f[8] = {va.x, va.y, va.z, va.w, vb.x, vb.y, vb.z, vb.w};
                uint32_t h[4], l[4];
                #pragma unroll
                for (int q = 0; q < 4; ++q) {
                    const unsigned short h0 = bfbits(f[2 * q]);
                    const unsigned short h1 = bfbits(f[2 * q + 1]);
                    const unsigned short l0 = bfbits(f[2 * q] - bf2f(h0));
                    const unsigned short l1 = bfbits(f[2 * q + 1] - bf2f(h1));
                    h[q] = (uint32_t)h0 | ((uint32_t)h1 << 16);
                    l[q] = (uint32_t)l0 | ((uint32_t)l1 << 16);
                    s = fmaf(f[2 * q], f[2 * q], s);
                    s = fmaf(f[2 * q + 1], f[2 * q + 1], s);
                }
                const int choff = ((j ^ (nn & 7)) << 4);
                *(uint4*)(smem + O_B0 + nn * 256 + choff) = make_uint4(h[0], h[1], h[2], h[3]);
                *(uint4*)(smem + O_B1 + nn * 256 + choff) = make_uint4(l[0], l[1], l[2], l[3]);
            }
            wsq[nn] = s;
        }
        __syncthreads();

        // ------------- tensor GEMM: 3-pass bf16, warp tile 32x64 -------------
        float acc[2][8][4];
        #pragma unroll
        for (int f = 0; f < 2; ++f)
            #pragma unroll
            for (int g = 0; g < 8; ++g)
                #pragma unroll
                for (int e = 0; e < 4; ++e) acc[f][g][e] = 0.0f;

        #pragma unroll
        for (int ks = 0; ks < 8; ++ks) {
            const uint32_t choff = (uint32_t)((((ks * 2 + kmi) ^ r)) << 4);
            uint32_t A0[2][4], A1[2][4], B0[4][4], B1[4][4];
            ldsm4(A0[0][0], A0[0][1], A0[0][2], A0[0][3], aA0 + rowA0 + choff);
            ldsm4(A0[1][0], A0[1][1], A0[1][2], A0[1][3], aA0 + rowA1 + choff);
            ldsm4(A1[0][0], A1[0][1], A1[0][2], A1[0][3], aA1 + rowA0 + choff);
            ldsm4(A1[1][0], A1[1][1], A1[1][2], A1[1][3], aA1 + rowA1 + choff);
            #pragma unroll
            for (int u = 0; u < 4; ++u) {
                ldsm4(B0[u][0], B0[u][1], B0[u][2], B0[u][3], aB0 + rowB[u] + choff);
                ldsm4(B1[u][0], B1[u][1], B1[u][2], B1[u][3], aB1 + rowB[u] + choff);
            }
            #pragma unroll
            for (int f = 0; f < 2; ++f)
                #pragma unroll
                for (int u = 0; u < 4; ++u)
                    #pragma unroll
                    for (int v = 0; v < 2; ++v) {
                        float* ac = acc[f][u * 2 + v];
                        mma_bf16(ac, A0[f], B0[u][v], B0[u][2 + v]);
                        mma_bf16(ac, A0[f], B1[u][v], B1[u][2 + v]);
                        mma_bf16(ac, A1[f], B0[u][v], B0[u][2 + v]);
                        // A1*B1 dropped: |a1*b1| <= 2^-18 |y||w| — negligible
                    }
        }

        // ------------- epilogue: exp + direct global stores ------------------
        #pragma unroll
        for (int f = 0; f < 2; ++f) {
            const int q0 = f * 2;
            const int q1 = f * 2 + 1;
            const float ys0 = ysf[q0];
            const float ys1 = ysf[q1];
            #pragma unroll
            for (int u = 0; u < 4; ++u)
                #pragma unroll
                for (int v = 0; v < 2; ++v) {
                    const float* ac = acc[f][u * 2 + v];
                    const int cb = n0 + u * 16 + v * 8 + 2 * c;
                    const float ws0 = wsq[cb];
                    const float ws1 = wsq[cb + 1];
                    const long co0 = (long)(col0 + cb) * PVOL;
                    const long co1 = co0 + PVOL;
                    if (ovalid[q0]) {
                        out[obase[q0] + co0] = __expf(fmaf(2.0f, ac[0], -(ys0 + ws0)));
                        out[obase[q0] + co1] = __expf(fmaf(2.0f, ac[1], -(ys0 + ws1)));
                    }
                    if (ovalid[q1]) {
                        out[obase[q1] + co0] = __expf(fmaf(2.0f, ac[2], -(ys1 + ws0)));
                        out[obase[q1] + co1] = __expf(fmaf(2.0f, ac[3], -(ys1 + ws1)));
                    }
                }
        }
        __syncthreads();   // all B reads done before next fill overwrites
    }
}

extern "C" void kernel_launch(void* const* d_in, const int* in_sizes, int n_in,
                              void* d_out, int out_size) {
    const float* x = (const float*)d_in[0];
    const float* w = (const float*)d_in[1];
    float* out = (float*)d_out;

    cudaFuncSetAttribute(gk_kernel, cudaFuncAttributeMaxDynamicSharedMemorySize,
                         SMEM_BYTES);
    dim3 grid((MROWS + BM - 1) / BM, 1);   // 1862
    gk_kernel<<<grid, NT, SMEM_BYTES>>>(x, w, out);
}

// round 17
// speedup vs baseline: 1.0116x; 1.0116x over previous
#include <cuda_runtime.h>
#include <cuda_bf16.h>
#include <cstdint>

#define PVOL   29791
#define MROWS  119164
#define D1     512
#define KK     128
#define BM     96
#define BN     64
#define NCOL   8
#define NT     192

// smem byte offsets
#define O_A0    0              // 96x128 bf16 = 24576
#define O_A1    24576
#define O_B     49152          // 2 stages x (B0,B1) x 16384 = 65536
#define O_YSQP  81920          // alias of B stage1 (safe: used before iter0's fill(1))
#define O_YSQ   114688         // 96 f32
#define O_WSQ   115072         // 2 stages x 64 f32 = 512
#define SMEM_BYTES 115584

// bf16 element index with 16B-chunk XOR swizzle (row&7)
__device__ __forceinline__ int idx16(int row, int k) {
    return row * 128 + ((((k >> 3) ^ (row & 7))) << 3) + (k & 7);
}

__device__ __forceinline__ uint32_t s2u(const void* p) {
    uint32_t a;
    asm("{ .reg .u64 t; cvta.to.shared.u64 t, %1; cvt.u32.u64 %0, t; }" : "=r"(a) : "l"(p));
    return a;
}
__device__ __forceinline__ void ldsm4(uint32_t& r0, uint32_t& r1, uint32_t& r2, uint32_t& r3,
                                      uint32_t addr) {
    asm volatile("ldmatrix.sync.aligned.m8n8.x4.shared.b16 {%0,%1,%2,%3}, [%4];"
                 : "=r"(r0), "=r"(r1), "=r"(r2), "=r"(r3) : "r"(addr));
}
__device__ __forceinline__ void mma_bf16(float* d, const uint32_t* a, uint32_t b0, uint32_t b1) {
    asm volatile(
        "mma.sync.aligned.m16n8k16.row.col.f32.bf16.bf16.f32 "
        "{%0,%1,%2,%3}, {%4,%5,%6,%7}, {%8,%9}, {%0,%1,%2,%3};"
        : "+f"(d[0]), "+f"(d[1]), "+f"(d[2]), "+f"(d[3])
        : "r"(a[0]), "r"(a[1]), "r"(a[2]), "r"(a[3]), "r"(b0), "r"(b1));
}
__device__ __forceinline__ unsigned short bfbits(float v) {
    return __bfloat16_as_ushort(__float2bfloat16(v));
}
__device__ __forceinline__ float bf2f(unsigned short u) {
    __nv_bfloat16_raw raw; raw.x = u;
    return __bfloat162float(*(__nv_bfloat16*)&raw);
}

// Fill one B stage (64 cols x 128 k, 2-term bf16) + wsq; 64 threads active.
__device__ __forceinline__ void fill_B(char* smem, const float* __restrict__ w,
                                       int col0, int stage, int tid) {
    if (tid < 64) {
        const int nn = tid;
        char* b0 = smem + O_B + stage * 32768;
        char* b1 = b0 + 16384;
        float* wsq = (float*)(smem + O_WSQ) + stage * 64;
        const float* wr = w + (long)(col0 + nn) * KK;
        float s = 0.0f;
        #pragma unroll 4
        for (int j = 0; j < 16; ++j) {           // 8 k per chunk
            const float4 va = *(const float4*)(wr + j * 8);
            const float4 vb = *(const float4*)(wr + j * 8 + 4);
            const float f[8] = {va.x, va.y, va.z, va.w, vb.x, vb.y, vb.z, vb.w};
            uint32_t h[4], l[4];
            #pragma unroll
            for (int q = 0; q < 4; ++q) {
                const unsigned short h0 = bfbits(f[2 * q]);
                const unsigned short h1 = bfbits(f[2 * q + 1]);
                const unsigned short l0 = bfbits(f[2 * q] - bf2f(h0));
                const unsigned short l1 = bfbits(f[2 * q + 1] - bf2f(h1));
                h[q] = (uint32_t)h0 | ((uint32_t)h1 << 16);
                l[q] = (uint32_t)l0 | ((uint32_t)l1 << 16);
                s = fmaf(f[2 * q], f[2 * q], s);
                s = fmaf(f[2 * q + 1], f[2 * q + 1], s);
            }
            const int choff = ((j ^ (nn & 7)) << 4);
            *(uint4*)(b0 + nn * 256 + choff) = make_uint4(h[0], h[1], h[2], h[3]);
            *(uint4*)(b1 + nn * 256 + choff) = make_uint4(l[0], l[1], l[2], l[3]);
        }
        wsq[nn] = s;
    }
}

__global__ __launch_bounds__(NT, 2)
void gk_kernel(const float* __restrict__ x, const float* __restrict__ w,
               float* __restrict__ out) {
    extern __shared__ __align__(16) char smem[];
    uint16_t* sA0 = (uint16_t*)(smem + O_A0);
    uint16_t* sA1 = (uint16_t*)(smem + O_A1);
    float*    ysqp = (float*)(smem + O_YSQP);
    float*    ysq  = (float*)(smem + O_YSQ);

    const uint32_t aA0 = s2u(smem + O_A0);
    const uint32_t aA1 = s2u(smem + O_A1);
    const uint32_t aB  = s2u(smem + O_B);

    const int tid  = threadIdx.x;
    const int wid  = tid >> 5;
    const int lane = tid & 31;
    const int row0 = blockIdx.x * BM;

    // ---------------- gather A -> 2-term bf16 tiles + ||y||^2 ----------------
    {
        const int half = tid >= 96 ? 1 : 0;      // kw bit
        const int m    = tid - half * 96;
        const int row  = row0 + m;
        float s = 0.0f;
        if (row < MROWS) {
            const int n   = row / PVOL;
            const int p   = row - n * PVOL;
            const int d   = p / 961;
            const int rem = p - d * 961;
            const int h   = rem / 31;
            const int wx  = rem - h * 31;
            const long base = (long)n * 524288 + d * 1024 + h * 32 + wx + half;
            #pragma unroll 4
            for (int it = 0; it < 64; ++it) {
                const int c  = it >> 2;
                const int kd = (it >> 1) & 1;
                const int kh = it & 1;
                const int k  = c * 8 + kd * 4 + kh * 2 + half;
                const float v = x[base + (long)c * 32768 + kd * 1024 + kh * 32];
                const unsigned short u0 = bfbits(v);
                const unsigned short u1 = bfbits(v - bf2f(u0));
                const int o = idx16(m, k);
                sA0[o] = u0;
                sA1[o] = u1;
                s = fmaf(v, v, s);
            }
        } else {
            #pragma unroll 4
            for (int it = 0; it < 64; ++it) {
                const int k = (it >> 2) * 8 + (((it >> 1) & 1) << 2) + ((it & 1) << 1) + half;
                const int o = idx16(m, k);
                sA0[o] = 0;
                sA1[o] = 0;
            }
        }
        ysqp[half * 96 + m] = s;
    }
    __syncthreads();
    if (tid < 96) ysq[tid] = ysqp[tid] + ysqp[96 + tid];
    // fill B stage 0 for iter 0 (ysqp alias region not touched: stage 0)
    fill_B(smem, w, 0, 0, tid);
    __syncthreads();

    // ---- per-warp fragment geometry: warp tile 32x32, grid 3(m) x 2(n) ----
    const int m0 = (wid >> 1) * 32;
    const int n0 = (wid & 1) * 32;
    const int r    = lane & 7;
    const int midx = lane >> 3;
    const int mi1  = (midx & 1) * 8;
    const int kmi  = midx >> 1;
    const uint32_t rowA0 = (uint32_t)(m0 + mi1 + r) * 256u;
    const uint32_t rowA1 = rowA0 + 16u * 256u;
    const uint32_t rowB0 = (uint32_t)(n0 + mi1 + r) * 256u;
    const uint32_t rowB1 = rowB0 + 16u * 256u;

    const int c  = lane & 3;
    const int rg = lane >> 2;

    // ---- hoisted per-thread output rows + ||y||^2 ----
    long obase[4];
    bool ovalid[4];
    float ysf[4];
    #pragma unroll
    for (int q = 0; q < 4; ++q) {
        const int mloc = m0 + q * 8 + rg;
        const int row  = row0 + mloc;
        ysf[q] = ysq[mloc];
        ovalid[q] = row < MROWS;
        if (ovalid[q]) {
            const int n = row / PVOL;
            const int p = row - n * PVOL;
            obase[q] = (long)n * D1 * PVOL + p;
        } else obase[q] = 0;
    }

    for (int iter = 0; iter < NCOL; ++iter) {
        const int col0  = iter * BN;
        const int stage = iter & 1;
        const uint32_t aB0 = aB + stage * 32768u;
        const uint32_t aB1 = aB0 + 16384u;
        const float* wsq = (const float*)(smem + O_WSQ) + stage * 64;

        // ------------- tensor GEMM: 3-pass bf16, reads B[stage] --------------
        float acc[2][4][4];
        #pragma unroll
        for (int f = 0; f < 2; ++f)
            #pragma unroll
            for (int g = 0; g < 4; ++g)
                #pragma unroll
                for (int e = 0; e < 4; ++e) acc[f][g][e] = 0.0f;

        #pragma unroll
        for (int ks = 0; ks < 8; ++ks) {
            const uint32_t choff = (uint32_t)((((ks * 2 + kmi) ^ r)) << 4);
            uint32_t A0[2][4], A1[2][4], B0[2][4], B1[2][4];
            ldsm4(A0[0][0], A0[0][1], A0[0][2], A0[0][3], aA0 + rowA0 + choff);
            ldsm4(A0[1][0], A0[1][1], A0[1][2], A0[1][3], aA0 + rowA1 + choff);
            ldsm4(A1[0][0], A1[0][1], A1[0][2], A1[0][3], aA1 + rowA0 + choff);
            ldsm4(A1[1][0], A1[1][1], A1[1][2], A1[1][3], aA1 + rowA1 + choff);
            ldsm4(B0[0][0], B0[0][1], B0[0][2], B0[0][3], aB0 + rowB0 + choff);
            ldsm4(B0[1][0], B0[1][1], B0[1][2], B0[1][3], aB0 + rowB1 + choff);
            ldsm4(B1[0][0], B1[0][1], B1[0][2], B1[0][3], aB1 + rowB0 + choff);
            ldsm4(B1[1][0], B1[1][1], B1[1][2], B1[1][3], aB1 + rowB1 + choff);

            #pragma unroll
            for (int f = 0; f < 2; ++f)
                #pragma unroll
                for (int u = 0; u < 2; ++u)
                    #pragma unroll
                    for (int v = 0; v < 2; ++v) {
                        float* ac = acc[f][u * 2 + v];
                        mma_bf16(ac, A0[f], B0[u][v], B0[u][2 + v]);
                        mma_bf16(ac, A0[f], B1[u][v], B1[u][2 + v]);
                        mma_bf16(ac, A1[f], B0[u][v], B0[u][2 + v]);
                        // A1*B1 dropped: |a1*b1| <= 2^-18 |y||w| — negligible
                    }
        }

        // ------------- prefetch next B stage (overlaps epilogue) -------------
        if (iter + 1 < NCOL)
            fill_B(smem, w, (iter + 1) * BN, stage ^ 1, tid);

        // ------------- epilogue: exp + direct global stores ------------------
        #pragma unroll
        for (int f = 0; f < 2; ++f) {
            const int q0 = f * 2;
            const int q1 = f * 2 + 1;
            const float ys0 = ysf[q0];
            const float ys1 = ysf[q1];
            #pragma unroll
            for (int u = 0; u < 2; ++u)
                #pragma unroll
                for (int v = 0; v < 2; ++v) {
                    const float* ac = acc[f][u * 2 + v];
                    const int cb = n0 + u * 16 + v * 8 + 2 * c;
                    const float ws0 = wsq[cb];
                    const float ws1 = wsq[cb + 1];
                    const long co0 = (long)(col0 + cb) * PVOL;
                    const long co1 = co0 + PVOL;
                    if (ovalid[q0]) {
                        out[obase[q0] + co0] = __expf(fmaf(2.0f, ac[0], -(ys0 + ws0)));
                        out[obase[q0] + co1] = __expf(fmaf(2.0f, ac[1], -(ys0 + ws1)));
                    }
                    if (ovalid[q1]) {
                        out[obase[q1] + co0] = __expf(fmaf(2.0f, ac[2], -(ys1 + ws0)));
                        out[obase[q1] + co1] = __expf(fmaf(2.0f, ac[3], -(ys1 + ws1)));
                    }
                }
        }
        __syncthreads();   // B[stage^1] + wsq[stage^1] ready for next iter
    }
}

extern "C" void kernel_launch(void* const* d_in, const int* in_sizes, int n_in,
                              void* d_out, int out_size) {
    const float* x = (const float*)d_in[0];
    const float* w = (const float*)d_in[1];
    float* out = (float*)d_out;

    cudaFuncSetAttribute(gk_kernel, cudaFuncAttributeMaxDynamicSharedMemorySize,
                         SMEM_BYTES);
    dim3 grid((MROWS + BM - 1) / BM, 1);   // 1242
    gk_kernel<<<grid, NT, SMEM_BYTES>>>(x, w, out);
}